// round 8
// baseline (speedup 1.0000x reference)
#include <cuda_runtime.h>
#include <cuda_bf16.h>
#include <math.h>

#define NN 50000
#define NE 800000
#define HD 128
#define NG 64
#define POOL_SPLIT 16

// ---------------- scratch (device globals; no runtime allocation) ----------------
__device__ int    g_rowptr[NN + 1];
__device__ int    g_fillptr[NN];
__device__ int2   g_csr[NE];            // .x = src index, .y = weight bits

__device__ float4 g_support[NN * 32];   // [NN, 128] viewed as [NN, 32] float4
__device__ float4 g_G1[NN * 32];
__device__ float4 g_G2[NN * 32];
__device__ float4 g_G3[NN * 32];

__device__ float g_ssup[NN];
__device__ float g_score[NN];

__device__ int   g_gcount[NG];
__device__ int   g_gstart[NG + 1];

__device__ float g_psum[NG * 3 * POOL_SPLIT * HD];
__device__ float g_pmax[NG * 3 * POOL_SPLIT * HD];
__device__ float g_pooled[NG * 768];   // [avg(384) | max(384)] per graph

__device__ __forceinline__ int clampi(int v, int lo, int hi) {
    return v < lo ? lo : (v > hi ? hi : v);
}

// ---- packed f32x2 helpers (Blackwell: 2x fp32 FMA throughput via one instr) ----
__device__ __forceinline__ unsigned long long pack2(float x, float y) {
    unsigned long long r;
    asm("mov.b64 %0, {%1, %2};" : "=l"(r) : "f"(x), "f"(y));
    return r;
}
__device__ __forceinline__ void ffma2(unsigned long long& d,
                                      unsigned long long a, unsigned long long b) {
    asm("fma.rn.f32x2 %0, %1, %2, %0;" : "+l"(d) : "l"(a), "l"(b));
}
__device__ __forceinline__ float2 unpack2(unsigned long long v) {
    float2 r;
    asm("mov.b64 {%0, %1}, %2;" : "=f"(r.x), "=f"(r.y) : "l"(v));
    return r;
}

// ---------------- CSR build (edge_index is int32: [2, NE] row-major) -------------
__global__ void k_zero() {
    int i = blockIdx.x * blockDim.x + threadIdx.x;
    if (i < NN) g_fillptr[i] = 0;
    if (i < NG) g_gcount[i] = 0;
}

__global__ void k_hist(const int* __restrict__ ei) {
    int i = blockIdx.x * blockDim.x + threadIdx.x;
    if (i < NE) {
        int d = clampi(ei[NE + i], 0, NN - 1);
        atomicAdd(&g_fillptr[d], 1);
    }
}

// Single-block scan: each of 1024 threads serially owns CHUNK elements,
// two shfl warp-scans produce per-thread offsets. One pass over the data.
__global__ void k_scan() {
    __shared__ int wsum[32];
    const int CHUNK = (NN + 1023) / 1024;      // 49
    int tid  = threadIdx.x;
    int lane = tid & 31, wid = tid >> 5;
    int base = tid * CHUNK;

    int sum = 0;
    for (int i = 0; i < CHUNK; i++) {
        int idx = base + i;
        if (idx < NN) sum += g_fillptr[idx];
    }
    // inclusive warp scan of per-thread sums
    int v = sum;
#pragma unroll
    for (int o = 1; o < 32; o <<= 1) {
        int t = __shfl_up_sync(0xffffffffu, v, o);
        if (lane >= o) v += t;
    }
    if (lane == 31) wsum[wid] = v;
    __syncthreads();
    if (wid == 0) {
        int s = wsum[lane];
#pragma unroll
        for (int o = 1; o < 32; o <<= 1) {
            int t = __shfl_up_sync(0xffffffffu, s, o);
            if (lane >= o) s += t;
        }
        wsum[lane] = s;
    }
    __syncthreads();

    int run = v - sum + (wid > 0 ? wsum[wid - 1] : 0);   // exclusive prefix
    for (int i = 0; i < CHUNK; i++) {
        int idx = base + i;
        if (idx < NN) {
            int d = g_fillptr[idx];
            g_rowptr[idx]  = run;
            g_fillptr[idx] = run;
            run += d;
        }
    }
    if (tid == 1023) g_rowptr[NN] = run;
}

__global__ void k_fill(const int* __restrict__ ei,
                       const float* __restrict__ ew) {
    int i = blockIdx.x * blockDim.x + threadIdx.x;
    if (i < NE) {
        int s = clampi(ei[i], 0, NN - 1);
        int d = clampi(ei[NE + i], 0, NN - 1);
        int pos = atomicAdd(&g_fillptr[d], 1);
        if (pos < NE) g_csr[pos] = make_int2(s, __float_as_int(ew[i]));
    }
}

// ---------------- dense GEMM: g_support = X @ W  (f32x2 packed FMA) -------------
// sel: 0 -> external x_in, 1 -> g_G1, 2 -> g_G2
// Block: 512 threads, 32 nodes. Thread owns 2 nodes x 4 output dims.
__global__ void k_gemm(const float* __restrict__ Xext,
                       const float* __restrict__ W, int sel) {
    __shared__ float xs[32 * HD];           // 16 KB
    const float* X = (sel == 0) ? Xext
                   : (sel == 1) ? (const float*)g_G1
                                : (const float*)g_G2;
    int n0 = blockIdx.x * 32;
    int t = threadIdx.x;

    int nvalid = NN - n0; if (nvalid > 32) nvalid = 32;
    for (int i = t; i < 32 * HD; i += 512) {
        int nl = i >> 7;
        xs[i] = (nl < nvalid) ? X[n0 * HD + i] : 0.0f;
    }
    __syncthreads();

    int rp = t >> 5;          // 0..15 (row pair)
    int j4 = t & 31;          // float4 column group
    const ulonglong2* W2 = (const ulonglong2*)W;   // row k: 32 x (2 packed f32x2)
    const float* xa_row = &xs[(2 * rp) * HD];
    const float* xb_row = &xs[(2 * rp + 1) * HD];

    unsigned long long accA01 = 0ull, accA23 = 0ull;   // bits(0.f,0.f)
    unsigned long long accB01 = 0ull, accB23 = 0ull;

#pragma unroll 8
    for (int k = 0; k < HD; k++) {
        ulonglong2 w = __ldg(&W2[k * 32 + j4]);
        float xa = xa_row[k];
        float xb = xb_row[k];
        unsigned long long xa2 = pack2(xa, xa);
        unsigned long long xb2 = pack2(xb, xb);
        ffma2(accA01, xa2, w.x);
        ffma2(accA23, xa2, w.y);
        ffma2(accB01, xb2, w.x);
        ffma2(accB23, xb2, w.y);
    }

    int na = n0 + 2 * rp, nb = na + 1;
    float2 a01 = unpack2(accA01), a23 = unpack2(accA23);
    float2 b01 = unpack2(accB01), b23 = unpack2(accB23);
    if (na < NN) g_support[na * 32 + j4] = make_float4(a01.x, a01.y, a23.x, a23.y);
    if (nb < NN) g_support[nb * 32 + j4] = make_float4(b01.x, b01.y, b23.x, b23.y);
}

// ---------------- SpMM gather + fused attention partial dot ---------------------
// out = relu(b + sum_e w_e * support[src_e]);  g_ssup[n] (+)= dot(out_row, wa_chunk)
// sel: 1 -> g_G1, 2 -> g_G2, 3 -> g_G3. One warp per node, lane = float4 chunk.
__global__ void k_spmm(const float* __restrict__ bias,
                       const float* __restrict__ wa_part, int sel) {
    int gt = blockIdx.x * blockDim.x + threadIdx.x;
    int n = gt >> 5;
    int lane = gt & 31;
    if (n >= NN) return;

    float4* out = (sel == 1) ? g_G1 : (sel == 2) ? g_G2 : g_G3;
    int beg = g_rowptr[n], end = g_rowptr[n + 1];

    float4 acc0 = make_float4(0.f, 0.f, 0.f, 0.f);
    float4 acc1 = make_float4(0.f, 0.f, 0.f, 0.f);

    int e = beg;
    for (; e + 2 <= end; e += 2) {
        int2 c0 = g_csr[e];
        int2 c1 = g_csr[e + 1];
        float4 v0 = __ldg(&g_support[c0.x * 32 + lane]);
        float4 v1 = __ldg(&g_support[c1.x * 32 + lane]);
        float w0 = __int_as_float(c0.y);
        float w1 = __int_as_float(c1.y);
        acc0.x += w0 * v0.x; acc0.y += w0 * v0.y; acc0.z += w0 * v0.z; acc0.w += w0 * v0.w;
        acc1.x += w1 * v1.x; acc1.y += w1 * v1.y; acc1.z += w1 * v1.z; acc1.w += w1 * v1.w;
    }
    if (e < end) {
        int2 c0 = g_csr[e];
        float4 v0 = __ldg(&g_support[c0.x * 32 + lane]);
        float w0 = __int_as_float(c0.y);
        acc0.x += w0 * v0.x; acc0.y += w0 * v0.y; acc0.z += w0 * v0.z; acc0.w += w0 * v0.w;
    }

    float4 b = ((const float4*)bias)[lane];
    float4 r;
    r.x = fmaxf(acc0.x + acc1.x + b.x, 0.f);
    r.y = fmaxf(acc0.y + acc1.y + b.y, 0.f);
    r.z = fmaxf(acc0.z + acc1.z + b.z, 0.f);
    r.w = fmaxf(acc0.w + acc1.w + b.w, 0.f);
    out[n * 32 + lane] = r;

    // fused partial of ssup[n] = h[n,:] . wa  (this layer's 128-dim chunk)
    float4 wv = ((const float4*)wa_part)[lane];
    float dot = r.x * wv.x + r.y * wv.y + r.z * wv.z + r.w * wv.w;
#pragma unroll
    for (int o = 16; o > 0; o >>= 1) dot += __shfl_down_sync(0xffffffffu, dot, o);
    if (lane == 0) {
        if (sel == 1) g_ssup[n] = dot;
        else          g_ssup[n] += dot;
    }
}

// ---------------- score: gather ssup over edges, tanh ---------------------------
__global__ void k_score(const float* __restrict__ ba) {
    int n = blockIdx.x * blockDim.x + threadIdx.x;
    if (n >= NN) return;
    int beg = g_rowptr[n], end = g_rowptr[n + 1];
    float acc = 0.f;
    for (int e = beg; e < end; e++) {
        int2 c = g_csr[e];
        acc += __int_as_float(c.y) * __ldg(&g_ssup[c.x]);
    }
    g_score[n] = tanhf(acc + ba[0]);
}

// ---------------- per-graph ranges (graph_indicator is int32) ----------------
__global__ void k_ghist(const int* __restrict__ gi) {
    int i = blockIdx.x * blockDim.x + threadIdx.x;
    if (i < NN) atomicAdd(&g_gcount[clampi(gi[i], 0, NG - 1)], 1);
}

__global__ void k_gscan() {
    g_gstart[0] = 0;
    for (int g = 0; g < NG; g++) g_gstart[g + 1] = g_gstart[g] + g_gcount[g];
}

// ---------------- pooling: avg + max of h*score per graph ----------------
__global__ void k_pool() {
    int bx = blockIdx.x;                 // (g, c, s)
    int g = bx / (3 * POOL_SPLIT);
    int c = (bx / POOL_SPLIT) % 3;
    int s = bx % POOL_SPLIT;
    int t = threadIdx.x;                 // dim within chunk

    int gs = g_gstart[g], ge = g_gstart[g + 1];
    const float* H = (c == 0) ? (const float*)g_G1
                   : (c == 1) ? (const float*)g_G2
                              : (const float*)g_G3;

    float sum = 0.f, mx = -INFINITY;
    for (int n = gs + s; n < ge; n += POOL_SPLIT) {
        float v = H[n * HD + t] * g_score[n];
        sum += v;
        mx = fmaxf(mx, v);
    }
    int idx = ((g * 3 + c) * POOL_SPLIT + s) * HD + t;
    g_psum[idx] = sum;
    g_pmax[idx] = mx;
}

__global__ void k_pool_reduce() {
    int bx = blockIdx.x;                 // (g, c)
    int g = bx / 3, c = bx % 3;
    int t = threadIdx.x;

    float sum = 0.f, mx = -INFINITY;
#pragma unroll
    for (int s = 0; s < POOL_SPLIT; s++) {
        int idx = ((g * 3 + c) * POOL_SPLIT + s) * HD + t;
        sum += g_psum[idx];
        mx = fmaxf(mx, g_pmax[idx]);
    }
    int cnt = g_gstart[g + 1] - g_gstart[g];
    float denom = (float)(cnt > 1 ? cnt : 1);
    int j = c * HD + t;
    g_pooled[g * 768 + j]       = sum / denom;
    g_pooled[g * 768 + 384 + j] = mx;
}

// ---------------- final: out[g] = relu(pooled[g] @ Wf + bf) ----------------
__global__ void k_final(const float* __restrict__ Wf,
                        const float* __restrict__ bf,
                        float* __restrict__ out) {
    int g = blockIdx.x;
    int t = threadIdx.x;
    const float* p = &g_pooled[g * 768];
    float acc = bf[t];
#pragma unroll 8
    for (int k = 0; k < 768; k++)
        acc += p[k] * __ldg(&Wf[k * HD + t]);
    out[g * HD + t] = fmaxf(acc, 0.f);
}

// ---------------- launch (pure kernel launches; graph-capturable) ----------------
extern "C" void kernel_launch(void* const* d_in, const int* in_sizes, int n_in,
                              void* d_out, int out_size) {
    const int*   edge_index = (const int*)d_in[0];     // int32 [2, NE]
    const float* edge_w     = (const float*)d_in[1];
    const float* x_in       = (const float*)d_in[2];
    const int*   gind       = (const int*)d_in[3];     // int32 [NN]
    const float* W1 = (const float*)d_in[4];
    const float* b1 = (const float*)d_in[5];
    const float* W2 = (const float*)d_in[6];
    const float* b2 = (const float*)d_in[7];
    const float* W3 = (const float*)d_in[8];
    const float* b3 = (const float*)d_in[9];
    const float* wa = (const float*)d_in[10];
    const float* ba = (const float*)d_in[11];
    const float* Wf = (const float*)d_in[12];
    const float* bf = (const float*)d_in[13];
    float* out = (float*)d_out;

    // CSR build
    k_zero<<<(NN + 255) / 256, 256>>>();
    k_hist<<<(NE + 255) / 256, 256>>>(edge_index);
    k_scan<<<1, 1024>>>();
    k_fill<<<(NE + 255) / 256, 256>>>(edge_index, edge_w);
    k_ghist<<<(NN + 255) / 256, 256>>>(gind);
    k_gscan<<<1, 1>>>();

    const int gemm_grid = (NN + 31) / 32;
    const int spmm_grid = (NN * 32 + 255) / 256;   // exactly NN warps

    // layer 1
    k_gemm<<<gemm_grid, 512>>>(x_in, W1, 0);
    k_spmm<<<spmm_grid, 256>>>(b1, wa + 0 * HD, 1);
    // layer 2
    k_gemm<<<gemm_grid, 512>>>(x_in, W2, 1);
    k_spmm<<<spmm_grid, 256>>>(b2, wa + 1 * HD, 2);
    // layer 3
    k_gemm<<<gemm_grid, 512>>>(x_in, W3, 2);
    k_spmm<<<spmm_grid, 256>>>(b3, wa + 2 * HD, 3);

    // attention score (ssup fused into spmm above)
    k_score<<<(NN + 255) / 256, 256>>>(ba);

    // pooling
    k_pool<<<NG * 3 * POOL_SPLIT, HD>>>();
    k_pool_reduce<<<NG * 3, HD>>>();

    // output head
    k_final<<<NG, HD>>>(Wf, bf, out);
}

// round 9
// speedup vs baseline: 1.0703x; 1.0703x over previous
#include <cuda_runtime.h>
#include <cuda_bf16.h>
#include <math.h>

#define NN 50000
#define NE 800000
#define HD 128
#define NG 64
#define POOL_SPLIT 16

// ---------------- scratch (device globals; no runtime allocation) ----------------
__device__ int    g_rowptr[NN + 1];
__device__ int    g_fillptr[NN];
__device__ int2   g_csr[NE];            // .x = src index, .y = weight bits

__device__ float4 g_support[NN * 32];   // [NN, 128] viewed as [NN, 32] float4
__device__ float4 g_G1[NN * 32];
__device__ float4 g_G2[NN * 32];
__device__ float4 g_G3[NN * 32];

__device__ float g_ssup[NN];
__device__ float g_score[NN];

__device__ int   g_gstart[NG + 1];

__device__ float g_psum[NG * 3 * POOL_SPLIT * HD];
__device__ float g_pmax[NG * 3 * POOL_SPLIT * HD];
__device__ float g_pooled[NG * 768];   // [avg(384) | max(384)] per graph

__device__ __forceinline__ int clampi(int v, int lo, int hi) {
    return v < lo ? lo : (v > hi ? hi : v);
}

// ---- packed f32x2 helpers ----
__device__ __forceinline__ unsigned long long pack2(float x, float y) {
    unsigned long long r;
    asm("mov.b64 %0, {%1, %2};" : "=l"(r) : "f"(x), "f"(y));
    return r;
}
__device__ __forceinline__ void ffma2(unsigned long long& d,
                                      unsigned long long a, unsigned long long b) {
    asm("fma.rn.f32x2 %0, %1, %2, %0;" : "+l"(d) : "l"(a), "l"(b));
}
__device__ __forceinline__ float2 unpack2(unsigned long long v) {
    float2 r;
    asm("mov.b64 {%0, %1}, %2;" : "=f"(r.x), "=f"(r.y) : "l"(v));
    return r;
}

// ---------------- CSR build (edge_index is int32: [2, NE] row-major) -------------
__global__ void k_zero() {
    int i = blockIdx.x * blockDim.x + threadIdx.x;
    if (i < NN) g_fillptr[i] = 0;
}

__global__ void k_hist(const int* __restrict__ ei) {
    int i = blockIdx.x * blockDim.x + threadIdx.x;
    if (i < NE) {
        int d = clampi(ei[NE + i], 0, NN - 1);
        atomicAdd(&g_fillptr[d], 1);
    }
}

// Single-block scan: 1024 threads, each serially owns CHUNK elements.
__global__ void k_scan() {
    __shared__ int wsum[32];
    const int CHUNK = (NN + 1023) / 1024;      // 49
    int tid  = threadIdx.x;
    int lane = tid & 31, wid = tid >> 5;
    int base = tid * CHUNK;

    int sum = 0;
    for (int i = 0; i < CHUNK; i++) {
        int idx = base + i;
        if (idx < NN) sum += g_fillptr[idx];
    }
    int v = sum;
#pragma unroll
    for (int o = 1; o < 32; o <<= 1) {
        int t = __shfl_up_sync(0xffffffffu, v, o);
        if (lane >= o) v += t;
    }
    if (lane == 31) wsum[wid] = v;
    __syncthreads();
    if (wid == 0) {
        int s = wsum[lane];
#pragma unroll
        for (int o = 1; o < 32; o <<= 1) {
            int t = __shfl_up_sync(0xffffffffu, s, o);
            if (lane >= o) s += t;
        }
        wsum[lane] = s;
    }
    __syncthreads();

    int run = v - sum + (wid > 0 ? wsum[wid - 1] : 0);   // exclusive prefix
    for (int i = 0; i < CHUNK; i++) {
        int idx = base + i;
        if (idx < NN) {
            int d = g_fillptr[idx];
            g_rowptr[idx]  = run;
            g_fillptr[idx] = run;
            run += d;
        }
    }
    if (tid == 1023) g_rowptr[NN] = run;
}

__global__ void k_fill(const int* __restrict__ ei,
                       const float* __restrict__ ew) {
    int i = blockIdx.x * blockDim.x + threadIdx.x;
    if (i < NE) {
        int s = clampi(ei[i], 0, NN - 1);
        int d = clampi(ei[NE + i], 0, NN - 1);
        int pos = atomicAdd(&g_fillptr[d], 1);
        if (pos < NE) g_csr[pos] = make_int2(s, __float_as_int(ew[i]));
    }
}

// ---------------- dense GEMM: g_support = X @ W  ---------------------------------
// 512 threads, 64 nodes/block. Thread owns 4 nodes x 4 output dims (f32x2 FMA).
// Halves W L1-load bytes per FMA vs 2-node version (L1 wavefront bound).
__global__ void k_gemm(const float* __restrict__ Xext,
                       const float* __restrict__ W, int sel) {
    __shared__ float xs[64 * HD];           // 32 KB
    const float* X = (sel == 0) ? Xext
                   : (sel == 1) ? (const float*)g_G1
                                : (const float*)g_G2;
    int n0 = blockIdx.x * 64;
    int t = threadIdx.x;

    int nvalid = NN - n0; if (nvalid > 64) nvalid = 64;
    for (int i = t; i < 64 * HD; i += 512) {
        int nl = i >> 7;
        xs[i] = (nl < nvalid) ? X[n0 * HD + i] : 0.0f;
    }
    __syncthreads();

    int rp = t >> 5;          // 0..15 -> node group of 4
    int j4 = t & 31;          // float4 column group
    const ulonglong2* W2 = (const ulonglong2*)W;
    const float* x0r = &xs[(4 * rp + 0) * HD];
    const float* x1r = &xs[(4 * rp + 1) * HD];
    const float* x2r = &xs[(4 * rp + 2) * HD];
    const float* x3r = &xs[(4 * rp + 3) * HD];

    unsigned long long a0_01 = 0ull, a0_23 = 0ull;
    unsigned long long a1_01 = 0ull, a1_23 = 0ull;
    unsigned long long a2_01 = 0ull, a2_23 = 0ull;
    unsigned long long a3_01 = 0ull, a3_23 = 0ull;

#pragma unroll 8
    for (int k = 0; k < HD; k++) {
        ulonglong2 w = __ldg(&W2[k * 32 + j4]);
        unsigned long long p0 = pack2(x0r[k], x0r[k]);
        unsigned long long p1 = pack2(x1r[k], x1r[k]);
        unsigned long long p2 = pack2(x2r[k], x2r[k]);
        unsigned long long p3 = pack2(x3r[k], x3r[k]);
        ffma2(a0_01, p0, w.x); ffma2(a0_23, p0, w.y);
        ffma2(a1_01, p1, w.x); ffma2(a1_23, p1, w.y);
        ffma2(a2_01, p2, w.x); ffma2(a2_23, p2, w.y);
        ffma2(a3_01, p3, w.x); ffma2(a3_23, p3, w.y);
    }

    int nb = n0 + 4 * rp;
    float2 q01, q23;
    if (nb + 0 < NN) { q01 = unpack2(a0_01); q23 = unpack2(a0_23);
        g_support[(nb + 0) * 32 + j4] = make_float4(q01.x, q01.y, q23.x, q23.y); }
    if (nb + 1 < NN) { q01 = unpack2(a1_01); q23 = unpack2(a1_23);
        g_support[(nb + 1) * 32 + j4] = make_float4(q01.x, q01.y, q23.x, q23.y); }
    if (nb + 2 < NN) { q01 = unpack2(a2_01); q23 = unpack2(a2_23);
        g_support[(nb + 2) * 32 + j4] = make_float4(q01.x, q01.y, q23.x, q23.y); }
    if (nb + 3 < NN) { q01 = unpack2(a3_01); q23 = unpack2(a3_23);
        g_support[(nb + 3) * 32 + j4] = make_float4(q01.x, q01.y, q23.x, q23.y); }
}

// ---------------- SpMM gather + fused attention partial dot ---------------------
// out = relu(b + sum_e w_e * support[src_e]);  ssup[n] (+)= dot(out_row, wa_chunk)
// One warp per node; 4-wide unroll for MLP.
__global__ void k_spmm(const float* __restrict__ bias,
                       const float* __restrict__ wa_part, int sel) {
    int gt = blockIdx.x * blockDim.x + threadIdx.x;
    int n = gt >> 5;
    int lane = gt & 31;
    if (n >= NN) return;

    float4* out = (sel == 1) ? g_G1 : (sel == 2) ? g_G2 : g_G3;
    int beg = g_rowptr[n], end = g_rowptr[n + 1];

    float4 acc0 = make_float4(0.f, 0.f, 0.f, 0.f);
    float4 acc1 = make_float4(0.f, 0.f, 0.f, 0.f);
    float4 acc2 = make_float4(0.f, 0.f, 0.f, 0.f);
    float4 acc3 = make_float4(0.f, 0.f, 0.f, 0.f);

    int e = beg;
    for (; e + 4 <= end; e += 4) {
        int2 c0 = g_csr[e];
        int2 c1 = g_csr[e + 1];
        int2 c2 = g_csr[e + 2];
        int2 c3 = g_csr[e + 3];
        float4 v0 = __ldg(&g_support[c0.x * 32 + lane]);
        float4 v1 = __ldg(&g_support[c1.x * 32 + lane]);
        float4 v2 = __ldg(&g_support[c2.x * 32 + lane]);
        float4 v3 = __ldg(&g_support[c3.x * 32 + lane]);
        float w0 = __int_as_float(c0.y), w1 = __int_as_float(c1.y);
        float w2 = __int_as_float(c2.y), w3 = __int_as_float(c3.y);
        acc0.x += w0 * v0.x; acc0.y += w0 * v0.y; acc0.z += w0 * v0.z; acc0.w += w0 * v0.w;
        acc1.x += w1 * v1.x; acc1.y += w1 * v1.y; acc1.z += w1 * v1.z; acc1.w += w1 * v1.w;
        acc2.x += w2 * v2.x; acc2.y += w2 * v2.y; acc2.z += w2 * v2.z; acc2.w += w2 * v2.w;
        acc3.x += w3 * v3.x; acc3.y += w3 * v3.y; acc3.z += w3 * v3.z; acc3.w += w3 * v3.w;
    }
    for (; e < end; e++) {
        int2 c0 = g_csr[e];
        float4 v0 = __ldg(&g_support[c0.x * 32 + lane]);
        float w0 = __int_as_float(c0.y);
        acc0.x += w0 * v0.x; acc0.y += w0 * v0.y; acc0.z += w0 * v0.z; acc0.w += w0 * v0.w;
    }

    float4 b = ((const float4*)bias)[lane];
    float4 r;
    r.x = fmaxf(acc0.x + acc1.x + acc2.x + acc3.x + b.x, 0.f);
    r.y = fmaxf(acc0.y + acc1.y + acc2.y + acc3.y + b.y, 0.f);
    r.z = fmaxf(acc0.z + acc1.z + acc2.z + acc3.z + b.z, 0.f);
    r.w = fmaxf(acc0.w + acc1.w + acc2.w + acc3.w + b.w, 0.f);
    out[n * 32 + lane] = r;

    // fused partial of ssup[n] = h[n,:] . wa  (this layer's 128-dim chunk)
    float4 wv = ((const float4*)wa_part)[lane];
    float dot = r.x * wv.x + r.y * wv.y + r.z * wv.z + r.w * wv.w;
#pragma unroll
    for (int o = 16; o > 0; o >>= 1) dot += __shfl_down_sync(0xffffffffu, dot, o);
    if (lane == 0) {
        if (sel == 1) g_ssup[n] = dot;
        else          g_ssup[n] += dot;
    }
}

// ---------------- score: gather ssup over edges, tanh ---------------------------
__global__ void k_score(const float* __restrict__ ba) {
    int n = blockIdx.x * blockDim.x + threadIdx.x;
    if (n >= NN) return;
    int beg = g_rowptr[n], end = g_rowptr[n + 1];
    float acc = 0.f;
    for (int e = beg; e < end; e++) {
        int2 c = g_csr[e];
        acc += __int_as_float(c.y) * __ldg(&g_ssup[c.x]);
    }
    g_score[n] = tanhf(acc + ba[0]);
}

// ---------------- per-graph ranges: binary search on sorted indicator ------------
__global__ void k_gbounds(const int* __restrict__ gi) {
    int g = threadIdx.x;
    if (g > NG) return;
    int lo = 0, hi = NN;
    while (lo < hi) {
        int m = (lo + hi) >> 1;
        if (gi[m] < g) lo = m + 1; else hi = m;
    }
    g_gstart[g] = lo;
}

// ---------------- pooling: avg + max of h*score per graph ----------------
__global__ void k_pool() {
    int bx = blockIdx.x;                 // (g, c, s)
    int g = bx / (3 * POOL_SPLIT);
    int c = (bx / POOL_SPLIT) % 3;
    int s = bx % POOL_SPLIT;
    int t = threadIdx.x;                 // dim within chunk

    int gs = g_gstart[g], ge = g_gstart[g + 1];
    const float* H = (c == 0) ? (const float*)g_G1
                   : (c == 1) ? (const float*)g_G2
                              : (const float*)g_G3;

    float sum = 0.f, mx = -INFINITY;
    for (int n = gs + s; n < ge; n += POOL_SPLIT) {
        float v = H[n * HD + t] * g_score[n];
        sum += v;
        mx = fmaxf(mx, v);
    }
    int idx = ((g * 3 + c) * POOL_SPLIT + s) * HD + t;
    g_psum[idx] = sum;
    g_pmax[idx] = mx;
}

__global__ void k_pool_reduce() {
    int bx = blockIdx.x;                 // (g, c)
    int g = bx / 3, c = bx % 3;
    int t = threadIdx.x;

    float sum = 0.f, mx = -INFINITY;
#pragma unroll
    for (int s = 0; s < POOL_SPLIT; s++) {
        int idx = ((g * 3 + c) * POOL_SPLIT + s) * HD + t;
        sum += g_psum[idx];
        mx = fmaxf(mx, g_pmax[idx]);
    }
    int cnt = g_gstart[g + 1] - g_gstart[g];
    float denom = (float)(cnt > 1 ? cnt : 1);
    int j = c * HD + t;
    g_pooled[g * 768 + j]       = sum / denom;
    g_pooled[g * 768 + 384 + j] = mx;
}

// ---------------- final: out[g] = relu(pooled[g] @ Wf + bf) ----------------
__global__ void k_final(const float* __restrict__ Wf,
                        const float* __restrict__ bf,
                        float* __restrict__ out) {
    int g = blockIdx.x;
    int t = threadIdx.x;
    const float* p = &g_pooled[g * 768];
    float acc = bf[t];
#pragma unroll 8
    for (int k = 0; k < 768; k++)
        acc += p[k] * __ldg(&Wf[k * HD + t]);
    out[g * HD + t] = fmaxf(acc, 0.f);
}

// ---------------- launch (pure kernel launches; graph-capturable) ----------------
extern "C" void kernel_launch(void* const* d_in, const int* in_sizes, int n_in,
                              void* d_out, int out_size) {
    const int*   edge_index = (const int*)d_in[0];     // int32 [2, NE]
    const float* edge_w     = (const float*)d_in[1];
    const float* x_in       = (const float*)d_in[2];
    const int*   gind       = (const int*)d_in[3];     // int32 [NN]
    const float* W1 = (const float*)d_in[4];
    const float* b1 = (const float*)d_in[5];
    const float* W2 = (const float*)d_in[6];
    const float* b2 = (const float*)d_in[7];
    const float* W3 = (const float*)d_in[8];
    const float* b3 = (const float*)d_in[9];
    const float* wa = (const float*)d_in[10];
    const float* ba = (const float*)d_in[11];
    const float* Wf = (const float*)d_in[12];
    const float* bf = (const float*)d_in[13];
    float* out = (float*)d_out;

    // CSR build (launches 0-3)
    k_zero<<<(NN + 255) / 256, 256>>>();
    k_hist<<<(NE + 255) / 256, 256>>>(edge_index);
    k_scan<<<1, 1024>>>();
    k_fill<<<(NE + 255) / 256, 256>>>(edge_index, edge_w);

    const int gemm_grid = (NN + 63) / 64;
    const int spmm_grid = (NN * 32 + 255) / 256;   // exactly NN warps

    // layers (launches 4-9: profiler window lands on gemm/spmm)
    k_gemm<<<gemm_grid, 512>>>(x_in, W1, 0);
    k_spmm<<<spmm_grid, 256>>>(b1, wa + 0 * HD, 1);
    k_gemm<<<gemm_grid, 512>>>(x_in, W2, 1);
    k_spmm<<<spmm_grid, 256>>>(b2, wa + 1 * HD, 2);
    k_gemm<<<gemm_grid, 512>>>(x_in, W3, 2);
    k_spmm<<<spmm_grid, 256>>>(b3, wa + 2 * HD, 3);

    // attention score (ssup fused into spmm above)
    k_score<<<(NN + 255) / 256, 256>>>(ba);

    // per-graph ranges + pooling
    k_gbounds<<<1, NG + 1>>>(gind);
    k_pool<<<NG * 3 * POOL_SPLIT, HD>>>();
    k_pool_reduce<<<NG * 3, HD>>>();

    // output head
    k_final<<<NG, HD>>>(Wf, bf, out);
}